// round 1
// baseline (speedup 1.0000x reference)
#include <cuda_runtime.h>
#include <math.h>

// Problem constants
#define B_   8
#define S_   1024
#define D_   1024
#define H_   16
#define KD_  64
#define VD_  64
#define NQK  2048          // H*KD*2
#define NV   1024          // H*VD
#define MROWS (B_*S_)      // 8192

// ---------------------------------------------------------------------------
// Scratch (static device arrays — no runtime allocation)
// ---------------------------------------------------------------------------
__device__ float g_qk [B_*S_*NQK];        // 64 MB  x @ W_qk^T + b
__device__ float g_v  [B_*S_*NV];         // 32 MB  x @ W_v^T  + b
__device__ float g_q  [B_*H_*S_*KD_];     // 32 MB  [b,h,s,kd]
__device__ float g_k  [B_*H_*S_*KD_];     // 32 MB
__device__ float g_vp [B_*H_*S_*VD_];     // 32 MB
__device__ float g_ao [B_*S_*NV];         // 32 MB  attention out, [b,s, h*64+vd]
__device__ float g_psum[512];
__device__ float g_psq [512];
__device__ float g_stats[16];             // per-batch {sum, sumsq}

// ---------------------------------------------------------------------------
// SGEMM: C[M,N] = A[M,1024] @ W[N,1024]^T + bias[N]
// 128x128 tile, BK=16, 256 threads, 8x8 per thread
// ---------------------------------------------------------------------------
__global__ __launch_bounds__(256, 2)
void sgemm_bias(const float* __restrict__ A, const float* __restrict__ W,
                const float* __restrict__ bias, float* __restrict__ C, int N)
{
    __shared__ float As[16][132];
    __shared__ float Bs[16][132];
    const int K = 1024;
    int tid = threadIdx.x;
    int tx = tid & 15, ty = tid >> 4;
    int m0 = blockIdx.y * 128, n0 = blockIdx.x * 128;

    float acc[8][8];
#pragma unroll
    for (int i = 0; i < 8; i++)
#pragma unroll
        for (int j = 0; j < 8; j++) acc[i][j] = 0.f;

    for (int k0 = 0; k0 < K; k0 += 16) {
#pragma unroll
        for (int l = 0; l < 2; l++) {
            int i4 = tid + l * 256;
            int r  = i4 >> 2;
            int c4 = (i4 & 3) * 4;
            float4 a = *reinterpret_cast<const float4*>(&A[(size_t)(m0 + r) * K + k0 + c4]);
            As[c4 + 0][r] = a.x; As[c4 + 1][r] = a.y;
            As[c4 + 2][r] = a.z; As[c4 + 3][r] = a.w;
            float4 b = *reinterpret_cast<const float4*>(&W[(size_t)(n0 + r) * K + k0 + c4]);
            Bs[c4 + 0][r] = b.x; Bs[c4 + 1][r] = b.y;
            Bs[c4 + 2][r] = b.z; Bs[c4 + 3][r] = b.w;
        }
        __syncthreads();
#pragma unroll
        for (int k = 0; k < 16; k++) {
            float ar[8], br[8];
            float4 t;
            t = *reinterpret_cast<float4*>(&As[k][ty * 8]);     ar[0]=t.x; ar[1]=t.y; ar[2]=t.z; ar[3]=t.w;
            t = *reinterpret_cast<float4*>(&As[k][ty * 8 + 4]); ar[4]=t.x; ar[5]=t.y; ar[6]=t.z; ar[7]=t.w;
            t = *reinterpret_cast<float4*>(&Bs[k][tx * 8]);     br[0]=t.x; br[1]=t.y; br[2]=t.z; br[3]=t.w;
            t = *reinterpret_cast<float4*>(&Bs[k][tx * 8 + 4]); br[4]=t.x; br[5]=t.y; br[6]=t.z; br[7]=t.w;
#pragma unroll
            for (int i = 0; i < 8; i++)
#pragma unroll
                for (int j = 0; j < 8; j++) acc[i][j] += ar[i] * br[j];
        }
        __syncthreads();
    }

#pragma unroll
    for (int i = 0; i < 8; i++) {
        int m = m0 + ty * 8 + i;
#pragma unroll
        for (int jj = 0; jj < 8; jj += 4) {
            int n = n0 + tx * 8 + jj;
            float4 o;
            o.x = acc[i][jj + 0] + bias[n + 0];
            o.y = acc[i][jj + 1] + bias[n + 1];
            o.z = acc[i][jj + 2] + bias[n + 2];
            o.w = acc[i][jj + 3] + bias[n + 3];
            *reinterpret_cast<float4*>(&C[(size_t)m * N + n]) = o;
        }
    }
}

// ---------------------------------------------------------------------------
// O-projection: C = A @ W_o^T + b_o + x, plus per-CTA partial LN stats
// ---------------------------------------------------------------------------
__global__ __launch_bounds__(256, 2)
void sgemm_oproj(const float* __restrict__ A, const float* __restrict__ W,
                 const float* __restrict__ bias, const float* __restrict__ x,
                 float* __restrict__ C)
{
    __shared__ float As[16][132];
    __shared__ float Bs[16][132];
    const int K = 1024, N = 1024;
    int tid = threadIdx.x;
    int tx = tid & 15, ty = tid >> 4;
    int m0 = blockIdx.y * 128, n0 = blockIdx.x * 128;

    float acc[8][8];
#pragma unroll
    for (int i = 0; i < 8; i++)
#pragma unroll
        for (int j = 0; j < 8; j++) acc[i][j] = 0.f;

    for (int k0 = 0; k0 < K; k0 += 16) {
#pragma unroll
        for (int l = 0; l < 2; l++) {
            int i4 = tid + l * 256;
            int r  = i4 >> 2;
            int c4 = (i4 & 3) * 4;
            float4 a = *reinterpret_cast<const float4*>(&A[(size_t)(m0 + r) * K + k0 + c4]);
            As[c4 + 0][r] = a.x; As[c4 + 1][r] = a.y;
            As[c4 + 2][r] = a.z; As[c4 + 3][r] = a.w;
            float4 b = *reinterpret_cast<const float4*>(&W[(size_t)(n0 + r) * K + k0 + c4]);
            Bs[c4 + 0][r] = b.x; Bs[c4 + 1][r] = b.y;
            Bs[c4 + 2][r] = b.z; Bs[c4 + 3][r] = b.w;
        }
        __syncthreads();
#pragma unroll
        for (int k = 0; k < 16; k++) {
            float ar[8], br[8];
            float4 t;
            t = *reinterpret_cast<float4*>(&As[k][ty * 8]);     ar[0]=t.x; ar[1]=t.y; ar[2]=t.z; ar[3]=t.w;
            t = *reinterpret_cast<float4*>(&As[k][ty * 8 + 4]); ar[4]=t.x; ar[5]=t.y; ar[6]=t.z; ar[7]=t.w;
            t = *reinterpret_cast<float4*>(&Bs[k][tx * 8]);     br[0]=t.x; br[1]=t.y; br[2]=t.z; br[3]=t.w;
            t = *reinterpret_cast<float4*>(&Bs[k][tx * 8 + 4]); br[4]=t.x; br[5]=t.y; br[6]=t.z; br[7]=t.w;
#pragma unroll
            for (int i = 0; i < 8; i++)
#pragma unroll
                for (int j = 0; j < 8; j++) acc[i][j] += ar[i] * br[j];
        }
        __syncthreads();
    }

    float lsum = 0.f, lsq = 0.f;
#pragma unroll
    for (int i = 0; i < 8; i++) {
        int m = m0 + ty * 8 + i;
#pragma unroll
        for (int jj = 0; jj < 8; jj += 4) {
            int n = n0 + tx * 8 + jj;
            float4 xr = *reinterpret_cast<const float4*>(&x[(size_t)m * N + n]);
            float4 o;
            o.x = acc[i][jj + 0] + bias[n + 0] + xr.x;
            o.y = acc[i][jj + 1] + bias[n + 1] + xr.y;
            o.z = acc[i][jj + 2] + bias[n + 2] + xr.z;
            o.w = acc[i][jj + 3] + bias[n + 3] + xr.w;
            *reinterpret_cast<float4*>(&C[(size_t)m * N + n]) = o;
            lsum += o.x + o.y + o.z + o.w;
            lsq  += o.x*o.x + o.y*o.y + o.z*o.z + o.w*o.w;
        }
    }
    // deterministic block reduction (no atomics)
#pragma unroll
    for (int off = 16; off > 0; off >>= 1) {
        lsum += __shfl_down_sync(0xffffffffu, lsum, off);
        lsq  += __shfl_down_sync(0xffffffffu, lsq,  off);
    }
    __shared__ float rs[8], rq[8];
    if ((tid & 31) == 0) { rs[tid >> 5] = lsum; rq[tid >> 5] = lsq; }
    __syncthreads();
    if (tid == 0) {
        float s = 0.f, q = 0.f;
#pragma unroll
        for (int w = 0; w < 8; w++) { s += rs[w]; q += rq[w]; }
        int p = blockIdx.y * 8 + blockIdx.x;   // 0..511, 64 per batch
        g_psum[p] = s; g_psq[p] = q;
    }
}

// ---------------------------------------------------------------------------
// Repack: de-interleave qk/v channel layouts into [b,h,s,64] contiguous
// q ch = kd*32 + h ; k ch = kd*32 + 16 + h ; v ch = vd*16 + h
// ---------------------------------------------------------------------------
__global__ void repack_kernel()
{
    __shared__ float sqk[2048 + 64];
    __shared__ float sv [1024 + 32];
    int bs = blockIdx.x;            // 0..8191
    int b = bs >> 10, s = bs & 1023;
    int tid = threadIdx.x;          // 256
    const float* qkrow = g_qk + (size_t)bs * NQK;
    const float* vrow  = g_v  + (size_t)bs * NV;
    for (int c = tid; c < 2048; c += 256) sqk[c + (c >> 5)] = qkrow[c];
    for (int c = tid; c < 1024; c += 256) sv [c + (c >> 5)] = vrow[c];
    __syncthreads();
    for (int idx = tid; idx < 1024; idx += 256) {
        int h = idx >> 6, kd = idx & 63;
        int cq = kd * 32 + h;
        int ck = cq + 16;
        int cv = kd * 16 + h;   // kd plays the role of vd here
        size_t o = ((size_t)(b * H_ + h) * S_ + s) * 64 + kd;
        g_q [o] = sqk[cq + (cq >> 5)];
        g_k [o] = sqk[ck + (ck >> 5)];
        g_vp[o] = sv [cv + (cv >> 5)];
    }
}

// ---------------------------------------------------------------------------
// Flash attention: CTA = (b, h, 128 q-rows); j-tiles of 64; online softmax
// ---------------------------------------------------------------------------
#define AT_SMEM_FLOATS (128*65 + 64*65 + 64*64 + 128*65)
__global__ __launch_bounds__(256, 2)
void attn_kernel()
{
    extern __shared__ float sm[];
    float* Qs  = sm;                 // [128][65]  (scaled by 1/8)
    float* Kst = Qs  + 128 * 65;     // [kd][j] pitch 65 (transposed)
    float* Vs  = Kst + 64 * 65;      // [j][vd] pitch 64
    float* Ps  = Vs  + 64 * 64;      // [128][65]

    int i0 = blockIdx.x * 128;
    int h  = blockIdx.y, b = blockIdx.z;
    int bh = b * H_ + h;
    const float* Qb = g_q  + ((size_t)bh * S_ + i0) * KD_;
    const float* Kb = g_k  + (size_t)bh * S_ * KD_;
    const float* Vb = g_vp + (size_t)bh * S_ * VD_;

    int tid = threadIdx.x;
    int tx = tid & 15, ty = tid >> 4;

    // load Q tile (scaled), float4 gmem reads, padded smem stores
    for (int idx = tid; idx < 2048; idx += 256) {       // float4 units
        int r = idx >> 4, c4 = (idx & 15) * 4;
        float4 q4 = *reinterpret_cast<const float4*>(&Qb[(size_t)r * 64 + c4]);
        Qs[r * 65 + c4 + 0] = q4.x * 0.125f;
        Qs[r * 65 + c4 + 1] = q4.y * 0.125f;
        Qs[r * 65 + c4 + 2] = q4.z * 0.125f;
        Qs[r * 65 + c4 + 3] = q4.w * 0.125f;
    }

    float m_[8], l_[8], accO[8][4];
#pragma unroll
    for (int i = 0; i < 8; i++) {
        m_[i] = -1e30f; l_[i] = 0.f;
#pragma unroll
        for (int j = 0; j < 4; j++) accO[i][j] = 0.f;
    }

    for (int j0 = 0; j0 < S_; j0 += 64) {
        // load K (transposed, padded) and V tiles
        for (int idx = tid; idx < 1024; idx += 256) {   // float4 units
            int r = idx >> 4, c4 = (idx & 15) * 4;
            float4 k4 = *reinterpret_cast<const float4*>(&Kb[(size_t)(j0 + r) * 64 + c4]);
            Kst[(c4 + 0) * 65 + r] = k4.x;
            Kst[(c4 + 1) * 65 + r] = k4.y;
            Kst[(c4 + 2) * 65 + r] = k4.z;
            Kst[(c4 + 3) * 65 + r] = k4.w;
            *reinterpret_cast<float4*>(&Vs[r * 64 + c4]) =
                *reinterpret_cast<const float4*>(&Vb[(size_t)(j0 + r) * 64 + c4]);
        }
        __syncthreads();

        // S tile = Q K^T   (rows ty*8+i, cols tx*4+j)
        float acc[8][4];
#pragma unroll
        for (int i = 0; i < 8; i++)
#pragma unroll
            for (int j = 0; j < 4; j++) acc[i][j] = 0.f;

        for (int kd = 0; kd < 64; kd++) {
            float qv[8], kv[4];
#pragma unroll
            for (int i = 0; i < 8; i++) qv[i] = Qs[(ty * 8 + i) * 65 + kd];
#pragma unroll
            for (int j = 0; j < 4; j++) kv[j] = Kst[kd * 65 + tx * 4 + j];
#pragma unroll
            for (int i = 0; i < 8; i++)
#pragma unroll
                for (int j = 0; j < 4; j++) acc[i][j] += qv[i] * kv[j];
        }

        // online softmax (row groups of 16 lanes: xor 1,2,4,8)
#pragma unroll
        for (int i = 0; i < 8; i++) {
            float tm = fmaxf(fmaxf(acc[i][0], acc[i][1]), fmaxf(acc[i][2], acc[i][3]));
            tm = fmaxf(tm, __shfl_xor_sync(0xffffffffu, tm, 1));
            tm = fmaxf(tm, __shfl_xor_sync(0xffffffffu, tm, 2));
            tm = fmaxf(tm, __shfl_xor_sync(0xffffffffu, tm, 4));
            tm = fmaxf(tm, __shfl_xor_sync(0xffffffffu, tm, 8));
            float mn = fmaxf(m_[i], tm);
            float sc = __expf(m_[i] - mn);
            float p0 = __expf(acc[i][0] - mn);
            float p1 = __expf(acc[i][1] - mn);
            float p2 = __expf(acc[i][2] - mn);
            float p3 = __expf(acc[i][3] - mn);
            float ps = p0 + p1 + p2 + p3;
            ps += __shfl_xor_sync(0xffffffffu, ps, 1);
            ps += __shfl_xor_sync(0xffffffffu, ps, 2);
            ps += __shfl_xor_sync(0xffffffffu, ps, 4);
            ps += __shfl_xor_sync(0xffffffffu, ps, 8);
            l_[i] = l_[i] * sc + ps;
            m_[i] = mn;
#pragma unroll
            for (int j = 0; j < 4; j++) accO[i][j] *= sc;
            int base = (ty * 8 + i) * 65 + tx * 4;
            Ps[base + 0] = p0; Ps[base + 1] = p1;
            Ps[base + 2] = p2; Ps[base + 3] = p3;
        }
        __syncthreads();

        // O += P V   (thread owns same rows, cols tx*4..tx*4+3)
        for (int c = 0; c < 64; c++) {
            float4 v4 = *reinterpret_cast<float4*>(&Vs[c * 64 + tx * 4]);
#pragma unroll
            for (int i = 0; i < 8; i++) {
                float p = Ps[(ty * 8 + i) * 65 + c];
                accO[i][0] += p * v4.x;
                accO[i][1] += p * v4.y;
                accO[i][2] += p * v4.z;
                accO[i][3] += p * v4.w;
            }
        }
        __syncthreads();
    }

    // normalize and write to [b, s, h*64 + vd]
#pragma unroll
    for (int i = 0; i < 8; i++) {
        float inv = 1.0f / l_[i];
        int srow = i0 + ty * 8 + i;
        float4 o;
        o.x = accO[i][0] * inv;
        o.y = accO[i][1] * inv;
        o.z = accO[i][2] * inv;
        o.w = accO[i][3] * inv;
        *reinterpret_cast<float4*>(
            &g_ao[((size_t)(b * S_ + srow)) * NV + h * 64 + tx * 4]) = o;
    }
}

// ---------------------------------------------------------------------------
// LN stats reduce: warp w = batch w, 64 partials each
// ---------------------------------------------------------------------------
__global__ void stats_reduce()
{
    int w = threadIdx.x >> 5, lane = threadIdx.x & 31;
    float s = g_psum[w * 64 + lane] + g_psum[w * 64 + 32 + lane];
    float q = g_psq [w * 64 + lane] + g_psq [w * 64 + 32 + lane];
#pragma unroll
    for (int off = 16; off > 0; off >>= 1) {
        s += __shfl_down_sync(0xffffffffu, s, off);
        q += __shfl_down_sync(0xffffffffu, q, off);
    }
    if (lane == 0) { g_stats[2 * w] = s; g_stats[2 * w + 1] = q; }
}

// ---------------------------------------------------------------------------
// LN finalize: y = (y - mean)*rsqrt(var+eps)*ln_w + ln_b (per batch)
// ---------------------------------------------------------------------------
__global__ void ln_finalize(float* __restrict__ y,
                            const float* __restrict__ lnw,
                            const float* __restrict__ lnb)
{
    int idx = blockIdx.x * 256 + threadIdx.x;    // float4 units, 2^21 total
    int b   = idx >> 18;                         // 2^18 float4 per batch
    int sd4 = idx & ((1 << 18) - 1);
    const float invn = 1.0f / 1048576.0f;
    float mean = g_stats[2 * b] * invn;
    float var  = g_stats[2 * b + 1] * invn - mean * mean;
    float inv  = rsqrtf(var + 1e-5f);
    float4 v  = reinterpret_cast<float4*>(y)[idx];
    float4 w  = reinterpret_cast<const float4*>(lnw)[sd4];
    float4 bb = reinterpret_cast<const float4*>(lnb)[sd4];
    v.x = (v.x - mean) * inv * w.x + bb.x;
    v.y = (v.y - mean) * inv * w.y + bb.y;
    v.z = (v.z - mean) * inv * w.z + bb.z;
    v.w = (v.w - mean) * inv * w.w + bb.w;
    reinterpret_cast<float4*>(y)[idx] = v;
}

// ---------------------------------------------------------------------------
// kernel_launch
// ---------------------------------------------------------------------------
extern "C" void kernel_launch(void* const* d_in, const int* in_sizes, int n_in,
                              void* d_out, int out_size)
{
    const float* x    = (const float*)d_in[0];
    const float* W_qk = (const float*)d_in[1];
    const float* b_qk = (const float*)d_in[2];
    const float* W_v  = (const float*)d_in[3];
    const float* b_v  = (const float*)d_in[4];
    const float* W_o  = (const float*)d_in[5];
    const float* b_o  = (const float*)d_in[6];
    const float* ln_w = (const float*)d_in[7];
    const float* ln_b = (const float*)d_in[8];
    float* out = (float*)d_out;

    void *p_qk, *p_v, *p_ao;
    cudaGetSymbolAddress(&p_qk, g_qk);
    cudaGetSymbolAddress(&p_v,  g_v);
    cudaGetSymbolAddress(&p_ao, g_ao);

    static bool attr_set = false;
    (void)attr_set;
    cudaFuncSetAttribute(attn_kernel, cudaFuncAttributeMaxDynamicSharedMemorySize,
                         AT_SMEM_FLOATS * 4);

    // 1) qk = x @ W_qk^T + b_qk   (8192 x 2048)
    sgemm_bias<<<dim3(NQK / 128, MROWS / 128), 256>>>(x, W_qk, b_qk, (float*)p_qk, NQK);
    // 2) v  = x @ W_v^T + b_v     (8192 x 1024)
    sgemm_bias<<<dim3(NV / 128, MROWS / 128), 256>>>(x, W_v, b_v, (float*)p_v, NV);
    // 3) repack into [b,h,s,64]
    repack_kernel<<<MROWS, 256>>>();
    // 4) flash attention
    attn_kernel<<<dim3(S_ / 128, H_, B_), 256, AT_SMEM_FLOATS * 4>>>();
    // 5) O-proj + bias + residual + partial LN stats
    sgemm_oproj<<<dim3(NV / 128, MROWS / 128), 256>>>((const float*)p_ao, W_o, b_o, x, out);
    // 6) reduce stats per batch
    stats_reduce<<<1, 256>>>();
    // 7) LayerNorm finalize
    ln_finalize<<<(B_ * S_ * D_ / 4) / 256, 256>>>(out, ln_w, ln_b);
}

// round 3
// speedup vs baseline: 1.5945x; 1.5945x over previous
#include <cuda_runtime.h>
#include <math.h>

// Problem constants
#define B_   8
#define S_   1024
#define D_   1024
#define H_   16
#define KD_  64
#define VD_  64
#define NQK  2048          // H*KD*2
#define NV   1024          // H*VD
#define MROWS (B_*S_)      // 8192

// ---------------------------------------------------------------------------
// Scratch (static device arrays — no runtime allocation)
// ---------------------------------------------------------------------------
__device__ float g_qk [B_*S_*NQK];        // x @ W_qk^T + b
__device__ float g_v  [B_*S_*NV];         // x @ W_v^T  + b
__device__ float g_q  [B_*H_*S_*KD_];     // [b,h,s,kd]
__device__ float g_k  [B_*H_*S_*KD_];
__device__ float g_vp [B_*H_*S_*VD_];
__device__ float g_ao [B_*S_*NV];         // attention out, [b,s, h*64+vd]
__device__ float g_psum[512];
__device__ float g_psq [512];
__device__ float g_stats[16];             // per-batch {sum, sumsq}

// ---------------------------------------------------------------------------
// TF32 helpers
// ---------------------------------------------------------------------------
__device__ __forceinline__ unsigned f2tf32(float f) {
    unsigned r;
    asm("cvt.rna.tf32.f32 %0, %1;" : "=r"(r) : "f"(f));
    return r;
}
__device__ __forceinline__ void mma_tf32(float& c0, float& c1, float& c2, float& c3,
                                         unsigned a0, unsigned a1, unsigned a2, unsigned a3,
                                         unsigned b0, unsigned b1) {
    asm volatile(
        "mma.sync.aligned.m16n8k8.row.col.f32.tf32.tf32.f32 "
        "{%0,%1,%2,%3}, {%4,%5,%6,%7}, {%8,%9}, {%0,%1,%2,%3};"
        : "+f"(c0), "+f"(c1), "+f"(c2), "+f"(c3)
        : "r"(a0), "r"(a1), "r"(a2), "r"(a3), "r"(b0), "r"(b1));
}

// ---------------------------------------------------------------------------
// TF32 tensor-core GEMM: C[M,N] = A[M,1024] @ W[N,1024]^T + bias[N]
// 128x128 CTA, 8 warps (2M x 4N), warp tile 64x32, BK=16
// Smem pitch 20 floats -> fragment LDS touches all 32 banks once (conflict-free)
// ---------------------------------------------------------------------------
#define GP 20   // smem pitch in floats

__global__ __launch_bounds__(256, 2)
void tgemm_bias(const float* __restrict__ A, const float* __restrict__ W,
                const float* __restrict__ bias, float* __restrict__ C, int N)
{
    __shared__ unsigned As[128 * GP];
    __shared__ unsigned Ws[128 * GP];
    const int K = 1024;
    int tid = threadIdx.x;
    int warpId = tid >> 5, lane = tid & 31;
    int wm = warpId >> 2, wn = warpId & 3;
    int g = lane >> 2, t = lane & 3;
    int m0 = blockIdx.y * 128, n0 = blockIdx.x * 128;

    float c[4][4][4];   // [tm][tn][frag]
#pragma unroll
    for (int i = 0; i < 4; i++)
#pragma unroll
        for (int j = 0; j < 4; j++)
#pragma unroll
            for (int f = 0; f < 4; f++) c[i][j][f] = 0.f;

    for (int k0 = 0; k0 < K; k0 += 16) {
#pragma unroll
        for (int l = 0; l < 2; l++) {
            int i4 = tid + l * 256;
            int r  = i4 >> 2;
            int c4 = (i4 & 3) * 4;
            float4 a = *reinterpret_cast<const float4*>(&A[(size_t)(m0 + r) * K + k0 + c4]);
            As[r * GP + c4 + 0] = f2tf32(a.x);
            As[r * GP + c4 + 1] = f2tf32(a.y);
            As[r * GP + c4 + 2] = f2tf32(a.z);
            As[r * GP + c4 + 3] = f2tf32(a.w);
            float4 b = *reinterpret_cast<const float4*>(&W[(size_t)(n0 + r) * K + k0 + c4]);
            Ws[r * GP + c4 + 0] = f2tf32(b.x);
            Ws[r * GP + c4 + 1] = f2tf32(b.y);
            Ws[r * GP + c4 + 2] = f2tf32(b.z);
            Ws[r * GP + c4 + 3] = f2tf32(b.w);
        }
        __syncthreads();

#pragma unroll
        for (int ks = 0; ks < 16; ks += 8) {
            unsigned af[4][4], bf[4][2];
#pragma unroll
            for (int tm = 0; tm < 4; tm++) {
                int row = wm * 64 + tm * 16 + g;
                af[tm][0] = As[row * GP + ks + t];
                af[tm][1] = As[(row + 8) * GP + ks + t];
                af[tm][2] = As[row * GP + ks + 4 + t];
                af[tm][3] = As[(row + 8) * GP + ks + 4 + t];
            }
#pragma unroll
            for (int tn = 0; tn < 4; tn++) {
                int rowb = wn * 32 + tn * 8 + g;
                bf[tn][0] = Ws[rowb * GP + ks + t];
                bf[tn][1] = Ws[rowb * GP + ks + 4 + t];
            }
#pragma unroll
            for (int tm = 0; tm < 4; tm++)
#pragma unroll
                for (int tn = 0; tn < 4; tn++)
                    mma_tf32(c[tm][tn][0], c[tm][tn][1], c[tm][tn][2], c[tm][tn][3],
                             af[tm][0], af[tm][1], af[tm][2], af[tm][3],
                             bf[tn][0], bf[tn][1]);
        }
        __syncthreads();
    }

#pragma unroll
    for (int tm = 0; tm < 4; tm++) {
        int row = m0 + wm * 64 + tm * 16 + g;
#pragma unroll
        for (int tn = 0; tn < 4; tn++) {
            int col = n0 + wn * 32 + tn * 8 + 2 * t;
            float2 o0, o1;
            o0.x = c[tm][tn][0] + bias[col];
            o0.y = c[tm][tn][1] + bias[col + 1];
            o1.x = c[tm][tn][2] + bias[col];
            o1.y = c[tm][tn][3] + bias[col + 1];
            *reinterpret_cast<float2*>(&C[(size_t)row * N + col])       = o0;
            *reinterpret_cast<float2*>(&C[(size_t)(row + 8) * N + col]) = o1;
        }
    }
}

// ---------------------------------------------------------------------------
// O-projection (TF32 MMA): C = A @ W_o^T + b_o + x, + per-CTA partial LN stats
// ---------------------------------------------------------------------------
__global__ __launch_bounds__(256, 2)
void tgemm_oproj(const float* __restrict__ A, const float* __restrict__ W,
                 const float* __restrict__ bias, const float* __restrict__ x,
                 float* __restrict__ C)
{
    __shared__ unsigned As[128 * GP];
    __shared__ unsigned Ws[128 * GP];
    const int K = 1024, N = 1024;
    int tid = threadIdx.x;
    int warpId = tid >> 5, lane = tid & 31;
    int wm = warpId >> 2, wn = warpId & 3;
    int g = lane >> 2, t = lane & 3;
    int m0 = blockIdx.y * 128, n0 = blockIdx.x * 128;

    float c[4][4][4];
#pragma unroll
    for (int i = 0; i < 4; i++)
#pragma unroll
        for (int j = 0; j < 4; j++)
#pragma unroll
            for (int f = 0; f < 4; f++) c[i][j][f] = 0.f;

    for (int k0 = 0; k0 < K; k0 += 16) {
#pragma unroll
        for (int l = 0; l < 2; l++) {
            int i4 = tid + l * 256;
            int r  = i4 >> 2;
            int c4 = (i4 & 3) * 4;
            float4 a = *reinterpret_cast<const float4*>(&A[(size_t)(m0 + r) * K + k0 + c4]);
            As[r * GP + c4 + 0] = f2tf32(a.x);
            As[r * GP + c4 + 1] = f2tf32(a.y);
            As[r * GP + c4 + 2] = f2tf32(a.z);
            As[r * GP + c4 + 3] = f2tf32(a.w);
            float4 b = *reinterpret_cast<const float4*>(&W[(size_t)(n0 + r) * K + k0 + c4]);
            Ws[r * GP + c4 + 0] = f2tf32(b.x);
            Ws[r * GP + c4 + 1] = f2tf32(b.y);
            Ws[r * GP + c4 + 2] = f2tf32(b.z);
            Ws[r * GP + c4 + 3] = f2tf32(b.w);
        }
        __syncthreads();

#pragma unroll
        for (int ks = 0; ks < 16; ks += 8) {
            unsigned af[4][4], bf[4][2];
#pragma unroll
            for (int tm = 0; tm < 4; tm++) {
                int row = wm * 64 + tm * 16 + g;
                af[tm][0] = As[row * GP + ks + t];
                af[tm][1] = As[(row + 8) * GP + ks + t];
                af[tm][2] = As[row * GP + ks + 4 + t];
                af[tm][3] = As[(row + 8) * GP + ks + 4 + t];
            }
#pragma unroll
            for (int tn = 0; tn < 4; tn++) {
                int rowb = wn * 32 + tn * 8 + g;
                bf[tn][0] = Ws[rowb * GP + ks + t];
                bf[tn][1] = Ws[rowb * GP + ks + 4 + t];
            }
#pragma unroll
            for (int tm = 0; tm < 4; tm++)
#pragma unroll
                for (int tn = 0; tn < 4; tn++)
                    mma_tf32(c[tm][tn][0], c[tm][tn][1], c[tm][tn][2], c[tm][tn][3],
                             af[tm][0], af[tm][1], af[tm][2], af[tm][3],
                             bf[tn][0], bf[tn][1]);
        }
        __syncthreads();
    }

    float lsum = 0.f, lsq = 0.f;
#pragma unroll
    for (int tm = 0; tm < 4; tm++) {
        int row = m0 + wm * 64 + tm * 16 + g;
#pragma unroll
        for (int tn = 0; tn < 4; tn++) {
            int col = n0 + wn * 32 + tn * 8 + 2 * t;
            float2 x0 = *reinterpret_cast<const float2*>(&x[(size_t)row * N + col]);
            float2 x1 = *reinterpret_cast<const float2*>(&x[(size_t)(row + 8) * N + col]);
            float2 o0, o1;
            o0.x = c[tm][tn][0] + bias[col]     + x0.x;
            o0.y = c[tm][tn][1] + bias[col + 1] + x0.y;
            o1.x = c[tm][tn][2] + bias[col]     + x1.x;
            o1.y = c[tm][tn][3] + bias[col + 1] + x1.y;
            *reinterpret_cast<float2*>(&C[(size_t)row * N + col])       = o0;
            *reinterpret_cast<float2*>(&C[(size_t)(row + 8) * N + col]) = o1;
            lsum += o0.x + o0.y + o1.x + o1.y;
            lsq  += o0.x*o0.x + o0.y*o0.y + o1.x*o1.x + o1.y*o1.y;
        }
    }
    // deterministic block reduction (no atomics)
#pragma unroll
    for (int off = 16; off > 0; off >>= 1) {
        lsum += __shfl_down_sync(0xffffffffu, lsum, off);
        lsq  += __shfl_down_sync(0xffffffffu, lsq,  off);
    }
    __shared__ float rs[8], rq[8];
    if (lane == 0) { rs[warpId] = lsum; rq[warpId] = lsq; }
    __syncthreads();
    if (tid == 0) {
        float s = 0.f, q = 0.f;
#pragma unroll
        for (int w = 0; w < 8; w++) { s += rs[w]; q += rq[w]; }
        int p = blockIdx.y * 8 + blockIdx.x;   // 0..511, 64 per batch
        g_psum[p] = s; g_psq[p] = q;
    }
}

// ---------------------------------------------------------------------------
// Repack: de-interleave qk/v channel layouts into [b,h,s,64] contiguous
// q ch = kd*32 + h ; k ch = kd*32 + 16 + h ; v ch = vd*16 + h
// ---------------------------------------------------------------------------
__global__ void repack_kernel()
{
    __shared__ float sqk[2048 + 64];
    __shared__ float sv [1024 + 32];
    int bs = blockIdx.x;            // 0..8191
    int b = bs >> 10, s = bs & 1023;
    int tid = threadIdx.x;          // 256
    const float* qkrow = g_qk + (size_t)bs * NQK;
    const float* vrow  = g_v  + (size_t)bs * NV;
    for (int c = tid; c < 2048; c += 256) sqk[c + (c >> 5)] = qkrow[c];
    for (int c = tid; c < 1024; c += 256) sv [c + (c >> 5)] = vrow[c];
    __syncthreads();
    for (int idx = tid; idx < 1024; idx += 256) {
        int h = idx >> 6, kd = idx & 63;
        int cq = kd * 32 + h;
        int ck = cq + 16;
        int cv = kd * 16 + h;
        size_t o = ((size_t)(b * H_ + h) * S_ + s) * 64 + kd;
        g_q [o] = sqk[cq + (cq >> 5)];
        g_k [o] = sqk[ck + (ck >> 5)];
        g_vp[o] = sv [cv + (cv >> 5)];
    }
}

// ---------------------------------------------------------------------------
// Flash attention: CTA = (b, h, 128 q-rows); j-tiles of 64; online softmax
// ---------------------------------------------------------------------------
#define AT_SMEM_FLOATS (128*65 + 64*65 + 64*64 + 128*65)
__global__ __launch_bounds__(256, 2)
void attn_kernel()
{
    extern __shared__ float sm[];
    float* Qs  = sm;                 // [128][65]  (scaled by 1/8)
    float* Kst = Qs  + 128 * 65;     // [kd][j] pitch 65 (transposed)
    float* Vs  = Kst + 64 * 65;      // [j][vd] pitch 64
    float* Ps  = Vs  + 64 * 64;      // [128][65]

    int i0 = blockIdx.x * 128;
    int h  = blockIdx.y, b = blockIdx.z;
    int bh = b * H_ + h;
    const float* Qb = g_q  + ((size_t)bh * S_ + i0) * KD_;
    const float* Kb = g_k  + (size_t)bh * S_ * KD_;
    const float* Vb = g_vp + (size_t)bh * S_ * VD_;

    int tid = threadIdx.x;
    int tx = tid & 15, ty = tid >> 4;

    for (int idx = tid; idx < 2048; idx += 256) {
        int r = idx >> 4, c4 = (idx & 15) * 4;
        float4 q4 = *reinterpret_cast<const float4*>(&Qb[(size_t)r * 64 + c4]);
        Qs[r * 65 + c4 + 0] = q4.x * 0.125f;
        Qs[r * 65 + c4 + 1] = q4.y * 0.125f;
        Qs[r * 65 + c4 + 2] = q4.z * 0.125f;
        Qs[r * 65 + c4 + 3] = q4.w * 0.125f;
    }

    float m_[8], l_[8], accO[8][4];
#pragma unroll
    for (int i = 0; i < 8; i++) {
        m_[i] = -1e30f; l_[i] = 0.f;
#pragma unroll
        for (int j = 0; j < 4; j++) accO[i][j] = 0.f;
    }

    for (int j0 = 0; j0 < S_; j0 += 64) {
        for (int idx = tid; idx < 1024; idx += 256) {
            int r = idx >> 4, c4 = (idx & 15) * 4;
            float4 k4 = *reinterpret_cast<const float4*>(&Kb[(size_t)(j0 + r) * 64 + c4]);
            Kst[(c4 + 0) * 65 + r] = k4.x;
            Kst[(c4 + 1) * 65 + r] = k4.y;
            Kst[(c4 + 2) * 65 + r] = k4.z;
            Kst[(c4 + 3) * 65 + r] = k4.w;
            *reinterpret_cast<float4*>(&Vs[r * 64 + c4]) =
                *reinterpret_cast<const float4*>(&Vb[(size_t)(j0 + r) * 64 + c4]);
        }
        __syncthreads();

        float acc[8][4];
#pragma unroll
        for (int i = 0; i < 8; i++)
#pragma unroll
            for (int j = 0; j < 4; j++) acc[i][j] = 0.f;

        for (int kd = 0; kd < 64; kd++) {
            float qv[8], kv[4];
#pragma unroll
            for (int i = 0; i < 8; i++) qv[i] = Qs[(ty * 8 + i) * 65 + kd];
#pragma unroll
            for (int j = 0; j < 4; j++) kv[j] = Kst[kd * 65 + tx * 4 + j];
#pragma unroll
            for (int i = 0; i < 8; i++)
#pragma unroll
                for (int j = 0; j < 4; j++) acc[i][j] += qv[i] * kv[j];
        }

#pragma unroll
        for (int i = 0; i < 8; i++) {
            float tm = fmaxf(fmaxf(acc[i][0], acc[i][1]), fmaxf(acc[i][2], acc[i][3]));
            tm = fmaxf(tm, __shfl_xor_sync(0xffffffffu, tm, 1));
            tm = fmaxf(tm, __shfl_xor_sync(0xffffffffu, tm, 2));
            tm = fmaxf(tm, __shfl_xor_sync(0xffffffffu, tm, 4));
            tm = fmaxf(tm, __shfl_xor_sync(0xffffffffu, tm, 8));
            float mn = fmaxf(m_[i], tm);
            float sc = __expf(m_[i] - mn);
            float p0 = __expf(acc[i][0] - mn);
            float p1 = __expf(acc[i][1] - mn);
            float p2 = __expf(acc[i][2] - mn);
            float p3 = __expf(acc[i][3] - mn);
            float ps = p0 + p1 + p2 + p3;
            ps += __shfl_xor_sync(0xffffffffu, ps, 1);
            ps += __shfl_xor_sync(0xffffffffu, ps, 2);
            ps += __shfl_xor_sync(0xffffffffu, ps, 4);
            ps += __shfl_xor_sync(0xffffffffu, ps, 8);
            l_[i] = l_[i] * sc + ps;
            m_[i] = mn;
#pragma unroll
            for (int j = 0; j < 4; j++) accO[i][j] *= sc;
            int base = (ty * 8 + i) * 65 + tx * 4;
            Ps[base + 0] = p0; Ps[base + 1] = p1;
            Ps[base + 2] = p2; Ps[base + 3] = p3;
        }
        __syncthreads();

        for (int c = 0; c < 64; c++) {
            float4 v4 = *reinterpret_cast<float4*>(&Vs[c * 64 + tx * 4]);
#pragma unroll
            for (int i = 0; i < 8; i++) {
                float p = Ps[(ty * 8 + i) * 65 + c];
                accO[i][0] += p * v4.x;
                accO[i][1] += p * v4.y;
                accO[i][2] += p * v4.z;
                accO[i][3] += p * v4.w;
            }
        }
        __syncthreads();
    }

#pragma unroll
    for (int i = 0; i < 8; i++) {
        float inv = 1.0f / l_[i];
        int srow = i0 + ty * 8 + i;
        float4 o;
        o.x = accO[i][0] * inv;
        o.y = accO[i][1] * inv;
        o.z = accO[i][2] * inv;
        o.w = accO[i][3] * inv;
        *reinterpret_cast<float4*>(
            &g_ao[((size_t)(b * S_ + srow)) * NV + h * 64 + tx * 4]) = o;
    }
}

// ---------------------------------------------------------------------------
// LN stats reduce + finalize
// ---------------------------------------------------------------------------
__global__ void stats_reduce()
{
    int w = threadIdx.x >> 5, lane = threadIdx.x & 31;
    float s = g_psum[w * 64 + lane] + g_psum[w * 64 + 32 + lane];
    float q = g_psq [w * 64 + lane] + g_psq [w * 64 + 32 + lane];
#pragma unroll
    for (int off = 16; off > 0; off >>= 1) {
        s += __shfl_down_sync(0xffffffffu, s, off);
        q += __shfl_down_sync(0xffffffffu, q, off);
    }
    if (lane == 0) { g_stats[2 * w] = s; g_stats[2 * w + 1] = q; }
}

__global__ void ln_finalize(float* __restrict__ y,
                            const float* __restrict__ lnw,
                            const float* __restrict__ lnb)
{
    int idx = blockIdx.x * 256 + threadIdx.x;
    int b   = idx >> 18;
    int sd4 = idx & ((1 << 18) - 1);
    const float invn = 1.0f / 1048576.0f;
    float mean = g_stats[2 * b] * invn;
    float var  = g_stats[2 * b + 1] * invn - mean * mean;
    float inv  = rsqrtf(var + 1e-5f);
    float4 v  = reinterpret_cast<float4*>(y)[idx];
    float4 w  = reinterpret_cast<const float4*>(lnw)[sd4];
    float4 bb = reinterpret_cast<const float4*>(lnb)[sd4];
    v.x = (v.x - mean) * inv * w.x + bb.x;
    v.y = (v.y - mean) * inv * w.y + bb.y;
    v.z = (v.z - mean) * inv * w.z + bb.z;
    v.w = (v.w - mean) * inv * w.w + bb.w;
    reinterpret_cast<float4*>(y)[idx] = v;
}

// ---------------------------------------------------------------------------
// kernel_launch
// ---------------------------------------------------------------------------
extern "C" void kernel_launch(void* const* d_in, const int* in_sizes, int n_in,
                              void* d_out, int out_size)
{
    const float* x    = (const float*)d_in[0];
    const float* W_qk = (const float*)d_in[1];
    const float* b_qk = (const float*)d_in[2];
    const float* W_v  = (const float*)d_in[3];
    const float* b_v  = (const float*)d_in[4];
    const float* W_o  = (const float*)d_in[5];
    const float* b_o  = (const float*)d_in[6];
    const float* ln_w = (const float*)d_in[7];
    const float* ln_b = (const float*)d_in[8];
    float* out = (float*)d_out;

    void *p_qk, *p_v, *p_ao;
    cudaGetSymbolAddress(&p_qk, g_qk);
    cudaGetSymbolAddress(&p_v,  g_v);
    cudaGetSymbolAddress(&p_ao, g_ao);

    cudaFuncSetAttribute(attn_kernel, cudaFuncAttributeMaxDynamicSharedMemorySize,
                         AT_SMEM_FLOATS * 4);

    // 1) qk = x @ W_qk^T + b_qk   (8192 x 2048) — TF32 MMA
    tgemm_bias<<<dim3(NQK / 128, MROWS / 128), 256>>>(x, W_qk, b_qk, (float*)p_qk, NQK);
    // 2) v  = x @ W_v^T + b_v     (8192 x 1024) — TF32 MMA
    tgemm_bias<<<dim3(NV / 128, MROWS / 128), 256>>>(x, W_v, b_v, (float*)p_v, NV);
    // 3) repack into [b,h,s,64]
    repack_kernel<<<MROWS, 256>>>();
    // 4) flash attention (fp32)
    attn_kernel<<<dim3(S_ / 128, H_, B_), 256, AT_SMEM_FLOATS * 4>>>();
    // 5) O-proj (TF32 MMA) + bias + residual + partial LN stats
    tgemm_oproj<<<dim3(NV / 128, MROWS / 128), 256>>>((const float*)p_ao, W_o, b_o, x, out);
    // 6) reduce stats per batch
    stats_reduce<<<1, 256>>>();
    // 7) LayerNorm finalize
    ln_finalize<<<(B_ * S_ * D_ / 4) / 256, 256>>>(out, ln_w, ln_b);
}

// round 4
// speedup vs baseline: 2.2843x; 1.4326x over previous
#include <cuda_runtime.h>
#include <math.h>

// Problem constants
#define B_   8
#define S_   1024
#define D_   1024
#define H_   16
#define KD_  64
#define VD_  64
#define NQK  2048          // H*KD*2
#define NV   1024          // H*VD
#define MROWS (B_*S_)      // 8192

// ---------------------------------------------------------------------------
// Scratch (static device arrays — no runtime allocation)
// ---------------------------------------------------------------------------
__device__ float g_qk [B_*S_*NQK];        // x @ W_qk^T + b
__device__ float g_v  [B_*S_*NV];         // x @ W_v^T  + b
__device__ float g_q  [B_*H_*S_*KD_];     // [b,h,s,kd]
__device__ float g_k  [B_*H_*S_*KD_];
__device__ float g_vp [B_*H_*S_*VD_];
__device__ float g_ao [B_*S_*NV];         // attention out, [b,s, h*64+vd]
__device__ float g_psum[512];
__device__ float g_psq [512];
__device__ float g_stats[16];             // per-batch {sum, sumsq}

// ---------------------------------------------------------------------------
// TF32 helpers
// ---------------------------------------------------------------------------
__device__ __forceinline__ unsigned f2tf32(float f) {
    unsigned r;
    asm("cvt.rna.tf32.f32 %0, %1;" : "=r"(r) : "f"(f));
    return r;
}
__device__ __forceinline__ void mma_tf32(float& c0, float& c1, float& c2, float& c3,
                                         unsigned a0, unsigned a1, unsigned a2, unsigned a3,
                                         unsigned b0, unsigned b1) {
    asm volatile(
        "mma.sync.aligned.m16n8k8.row.col.f32.tf32.tf32.f32 "
        "{%0,%1,%2,%3}, {%4,%5,%6,%7}, {%8,%9}, {%0,%1,%2,%3};"
        : "+f"(c0), "+f"(c1), "+f"(c2), "+f"(c3)
        : "r"(a0), "r"(a1), "r"(a2), "r"(a3), "r"(b0), "r"(b1));
}

// FMA-pipe exp2: no MUFU. arg clamped; 2^f poly (deg 6, err ~1e-7); 2^r via
// exponent-field add using the magic-number round trick.
__device__ __forceinline__ float fexp2(float y) {
    y = fmaxf(y, -80.f);
    float tt = y + 12582912.f;                 // 1.5*2^23: round-to-nearest
    float f  = y - (tt - 12582912.f);          // f in [-0.5, 0.5]
    float p  = 1.5403530393381610e-4f;
    p = p * f + 1.3333558146428443e-3f;
    p = p * f + 9.6181291076284770e-3f;
    p = p * f + 5.5504108664821580e-2f;
    p = p * f + 2.4022650695910071e-1f;
    p = p * f + 6.9314718055994531e-1f;
    p = p * f + 1.0f;
    return __int_as_float(__float_as_int(p) + (__float_as_int(tt) << 23));
}

// ---------------------------------------------------------------------------
// TF32 tensor-core GEMM: C[M,N] = A[M,1024] @ W[N,1024]^T + bias[N]
// 128x128 CTA, 8 warps (2M x 4N), warp tile 64x32, BK=16
// ---------------------------------------------------------------------------
#define GP 20   // smem pitch in floats

__global__ __launch_bounds__(256, 2)
void tgemm_bias(const float* __restrict__ A, const float* __restrict__ W,
                const float* __restrict__ bias, float* __restrict__ C, int N)
{
    __shared__ unsigned As[128 * GP];
    __shared__ unsigned Ws[128 * GP];
    const int K = 1024;
    int tid = threadIdx.x;
    int warpId = tid >> 5, lane = tid & 31;
    int wm = warpId >> 2, wn = warpId & 3;
    int g = lane >> 2, t = lane & 3;
    int m0 = blockIdx.y * 128, n0 = blockIdx.x * 128;

    float c[4][4][4];   // [tm][tn][frag]
#pragma unroll
    for (int i = 0; i < 4; i++)
#pragma unroll
        for (int j = 0; j < 4; j++)
#pragma unroll
            for (int f = 0; f < 4; f++) c[i][j][f] = 0.f;

    for (int k0 = 0; k0 < K; k0 += 16) {
#pragma unroll
        for (int l = 0; l < 2; l++) {
            int i4 = tid + l * 256;
            int r  = i4 >> 2;
            int c4 = (i4 & 3) * 4;
            float4 a = *reinterpret_cast<const float4*>(&A[(size_t)(m0 + r) * K + k0 + c4]);
            As[r * GP + c4 + 0] = f2tf32(a.x);
            As[r * GP + c4 + 1] = f2tf32(a.y);
            As[r * GP + c4 + 2] = f2tf32(a.z);
            As[r * GP + c4 + 3] = f2tf32(a.w);
            float4 b = *reinterpret_cast<const float4*>(&W[(size_t)(n0 + r) * K + k0 + c4]);
            Ws[r * GP + c4 + 0] = f2tf32(b.x);
            Ws[r * GP + c4 + 1] = f2tf32(b.y);
            Ws[r * GP + c4 + 2] = f2tf32(b.z);
            Ws[r * GP + c4 + 3] = f2tf32(b.w);
        }
        __syncthreads();

#pragma unroll
        for (int ks = 0; ks < 16; ks += 8) {
            unsigned af[4][4], bf[4][2];
#pragma unroll
            for (int tm = 0; tm < 4; tm++) {
                int row = wm * 64 + tm * 16 + g;
                af[tm][0] = As[row * GP + ks + t];
                af[tm][1] = As[(row + 8) * GP + ks + t];
                af[tm][2] = As[row * GP + ks + 4 + t];
                af[tm][3] = As[(row + 8) * GP + ks + 4 + t];
            }
#pragma unroll
            for (int tn = 0; tn < 4; tn++) {
                int rowb = wn * 32 + tn * 8 + g;
                bf[tn][0] = Ws[rowb * GP + ks + t];
                bf[tn][1] = Ws[rowb * GP + ks + 4 + t];
            }
#pragma unroll
            for (int tm = 0; tm < 4; tm++)
#pragma unroll
                for (int tn = 0; tn < 4; tn++)
                    mma_tf32(c[tm][tn][0], c[tm][tn][1], c[tm][tn][2], c[tm][tn][3],
                             af[tm][0], af[tm][1], af[tm][2], af[tm][3],
                             bf[tn][0], bf[tn][1]);
        }
        __syncthreads();
    }

#pragma unroll
    for (int tm = 0; tm < 4; tm++) {
        int row = m0 + wm * 64 + tm * 16 + g;
#pragma unroll
        for (int tn = 0; tn < 4; tn++) {
            int col = n0 + wn * 32 + tn * 8 + 2 * t;
            float2 o0, o1;
            o0.x = c[tm][tn][0] + bias[col];
            o0.y = c[tm][tn][1] + bias[col + 1];
            o1.x = c[tm][tn][2] + bias[col];
            o1.y = c[tm][tn][3] + bias[col + 1];
            *reinterpret_cast<float2*>(&C[(size_t)row * N + col])       = o0;
            *reinterpret_cast<float2*>(&C[(size_t)(row + 8) * N + col]) = o1;
        }
    }
}

// ---------------------------------------------------------------------------
// O-projection (TF32 MMA): C = A @ W_o^T + b_o + x, + per-CTA partial LN stats
// ---------------------------------------------------------------------------
__global__ __launch_bounds__(256, 2)
void tgemm_oproj(const float* __restrict__ A, const float* __restrict__ W,
                 const float* __restrict__ bias, const float* __restrict__ x,
                 float* __restrict__ C)
{
    __shared__ unsigned As[128 * GP];
    __shared__ unsigned Ws[128 * GP];
    const int K = 1024, N = 1024;
    int tid = threadIdx.x;
    int warpId = tid >> 5, lane = tid & 31;
    int wm = warpId >> 2, wn = warpId & 3;
    int g = lane >> 2, t = lane & 3;
    int m0 = blockIdx.y * 128, n0 = blockIdx.x * 128;

    float c[4][4][4];
#pragma unroll
    for (int i = 0; i < 4; i++)
#pragma unroll
        for (int j = 0; j < 4; j++)
#pragma unroll
            for (int f = 0; f < 4; f++) c[i][j][f] = 0.f;

    for (int k0 = 0; k0 < K; k0 += 16) {
#pragma unroll
        for (int l = 0; l < 2; l++) {
            int i4 = tid + l * 256;
            int r  = i4 >> 2;
            int c4 = (i4 & 3) * 4;
            float4 a = *reinterpret_cast<const float4*>(&A[(size_t)(m0 + r) * K + k0 + c4]);
            As[r * GP + c4 + 0] = f2tf32(a.x);
            As[r * GP + c4 + 1] = f2tf32(a.y);
            As[r * GP + c4 + 2] = f2tf32(a.z);
            As[r * GP + c4 + 3] = f2tf32(a.w);
            float4 b = *reinterpret_cast<const float4*>(&W[(size_t)(n0 + r) * K + k0 + c4]);
            Ws[r * GP + c4 + 0] = f2tf32(b.x);
            Ws[r * GP + c4 + 1] = f2tf32(b.y);
            Ws[r * GP + c4 + 2] = f2tf32(b.z);
            Ws[r * GP + c4 + 3] = f2tf32(b.w);
        }
        __syncthreads();

#pragma unroll
        for (int ks = 0; ks < 16; ks += 8) {
            unsigned af[4][4], bf[4][2];
#pragma unroll
            for (int tm = 0; tm < 4; tm++) {
                int row = wm * 64 + tm * 16 + g;
                af[tm][0] = As[row * GP + ks + t];
                af[tm][1] = As[(row + 8) * GP + ks + t];
                af[tm][2] = As[row * GP + ks + 4 + t];
                af[tm][3] = As[(row + 8) * GP + ks + 4 + t];
            }
#pragma unroll
            for (int tn = 0; tn < 4; tn++) {
                int rowb = wn * 32 + tn * 8 + g;
                bf[tn][0] = Ws[rowb * GP + ks + t];
                bf[tn][1] = Ws[rowb * GP + ks + 4 + t];
            }
#pragma unroll
            for (int tm = 0; tm < 4; tm++)
#pragma unroll
                for (int tn = 0; tn < 4; tn++)
                    mma_tf32(c[tm][tn][0], c[tm][tn][1], c[tm][tn][2], c[tm][tn][3],
                             af[tm][0], af[tm][1], af[tm][2], af[tm][3],
                             bf[tn][0], bf[tn][1]);
        }
        __syncthreads();
    }

    float lsum = 0.f, lsq = 0.f;
#pragma unroll
    for (int tm = 0; tm < 4; tm++) {
        int row = m0 + wm * 64 + tm * 16 + g;
#pragma unroll
        for (int tn = 0; tn < 4; tn++) {
            int col = n0 + wn * 32 + tn * 8 + 2 * t;
            float2 x0 = *reinterpret_cast<const float2*>(&x[(size_t)row * N + col]);
            float2 x1 = *reinterpret_cast<const float2*>(&x[(size_t)(row + 8) * N + col]);
            float2 o0, o1;
            o0.x = c[tm][tn][0] + bias[col]     + x0.x;
            o0.y = c[tm][tn][1] + bias[col + 1] + x0.y;
            o1.x = c[tm][tn][2] + bias[col]     + x1.x;
            o1.y = c[tm][tn][3] + bias[col + 1] + x1.y;
            *reinterpret_cast<float2*>(&C[(size_t)row * N + col])       = o0;
            *reinterpret_cast<float2*>(&C[(size_t)(row + 8) * N + col]) = o1;
            lsum += o0.x + o0.y + o1.x + o1.y;
            lsq  += o0.x*o0.x + o0.y*o0.y + o1.x*o1.x + o1.y*o1.y;
        }
    }
#pragma unroll
    for (int off = 16; off > 0; off >>= 1) {
        lsum += __shfl_down_sync(0xffffffffu, lsum, off);
        lsq  += __shfl_down_sync(0xffffffffu, lsq,  off);
    }
    __shared__ float rs[8], rq[8];
    if (lane == 0) { rs[warpId] = lsum; rq[warpId] = lsq; }
    __syncthreads();
    if (tid == 0) {
        float s = 0.f, q = 0.f;
#pragma unroll
        for (int w = 0; w < 8; w++) { s += rs[w]; q += rq[w]; }
        int p = blockIdx.y * 8 + blockIdx.x;   // 0..511, 64 per batch
        g_psum[p] = s; g_psq[p] = q;
    }
}

// ---------------------------------------------------------------------------
// Repack: de-interleave qk/v channel layouts into [b,h,s,64] contiguous
// ---------------------------------------------------------------------------
__global__ void repack_kernel()
{
    __shared__ float sqk[2048 + 64];
    __shared__ float sv [1024 + 32];
    int bs = blockIdx.x;            // 0..8191
    int b = bs >> 10, s = bs & 1023;
    int tid = threadIdx.x;          // 256
    const float* qkrow = g_qk + (size_t)bs * NQK;
    const float* vrow  = g_v  + (size_t)bs * NV;
    for (int c = tid; c < 2048; c += 256) sqk[c + (c >> 5)] = qkrow[c];
    for (int c = tid; c < 1024; c += 256) sv [c + (c >> 5)] = vrow[c];
    __syncthreads();
    for (int idx = tid; idx < 1024; idx += 256) {
        int h = idx >> 6, kd = idx & 63;
        int cq = kd * 32 + h;
        int ck = cq + 16;
        int cv = kd * 16 + h;
        size_t o = ((size_t)(b * H_ + h) * S_ + s) * 64 + kd;
        g_q [o] = sqk[cq + (cq >> 5)];
        g_k [o] = sqk[ck + (ck >> 5)];
        g_vp[o] = sv [cv + (cv >> 5)];
    }
}

// ---------------------------------------------------------------------------
// TF32 tensor-core flash attention.
// CTA = (b, h, 128 q-rows); 8 warps, warp owns 16 rows; j-tiles of 64.
// Q frags in registers; S=QK^T and O+=PV via m16n8k8; exp2 on FMA pipe.
// Smem pitch 68 (mod 32 = 4) -> Q/K/P fragment accesses conflict-free.
// ---------------------------------------------------------------------------
#define PA 68
#define AT_SMEM_BYTES (256 * PA * 4)   // Q/P[128] + K[64] + V[64] rows

__global__ __launch_bounds__(256, 2)
void attn_tc_kernel()
{
    extern __shared__ unsigned smu[];
    unsigned* Qs = smu;              // [128][PA]; reused as Ps after Q-frag load
    unsigned* Ks = smu + 128 * PA;   // [64][PA]   K[j][kd]
    unsigned* Vs = Ks + 64 * PA;     // [64][PA]   V[j][vd]

    int tid  = threadIdx.x;
    int warp = tid >> 5, lane = tid & 31;
    int g = lane >> 2, t = lane & 3;
    int i0 = blockIdx.x * 128;
    int h  = blockIdx.y, b = blockIdx.z;
    int bh = b * H_ + h;
    const float* Qb = g_q  + ((size_t)bh * S_ + i0) * KD_;
    const float* Kb = g_k  + (size_t)bh * S_ * KD_;
    const float* Vb = g_vp + (size_t)bh * S_ * VD_;
    const float QSCL = 0.125f * 1.4426950408889634f;  // 1/sqrt(64) * log2(e)

    // stage Q (scaled into log2 domain), convert to tf32
    for (int idx = tid; idx < 128 * 16; idx += 256) {
        int r = idx >> 4, c4 = (idx & 15) * 4;
        float4 q = *reinterpret_cast<const float4*>(&Qb[(size_t)r * 64 + c4]);
        Qs[r * PA + c4 + 0] = f2tf32(q.x * QSCL);
        Qs[r * PA + c4 + 1] = f2tf32(q.y * QSCL);
        Qs[r * PA + c4 + 2] = f2tf32(q.z * QSCL);
        Qs[r * PA + c4 + 3] = f2tf32(q.w * QSCL);
    }
    __syncthreads();

    // A-fragments of Q for this warp's 16 rows, all 8 k-steps -> registers
    int wr = warp * 16;
    unsigned qf[8][4];
#pragma unroll
    for (int k = 0; k < 8; k++) {
        qf[k][0] = Qs[(wr + g)     * PA + k * 8 + t];
        qf[k][1] = Qs[(wr + g + 8) * PA + k * 8 + t];
        qf[k][2] = Qs[(wr + g)     * PA + k * 8 + 4 + t];
        qf[k][3] = Qs[(wr + g + 8) * PA + k * 8 + 4 + t];
    }
    __syncthreads();            // Qs region now free -> becomes Ps
    unsigned* Ps = Qs;

    float accO[8][4];
#pragma unroll
    for (int n = 0; n < 8; n++)
#pragma unroll
        for (int f = 0; f < 4; f++) accO[n][f] = 0.f;
    float m0 = -1e30f, m1 = -1e30f, l0 = 0.f, l1 = 0.f;

    for (int j0 = 0; j0 < S_; j0 += 64) {
        // load K/V tiles (tf32)
        for (int idx = tid; idx < 64 * 16; idx += 256) {
            int r = idx >> 4, c4 = (idx & 15) * 4;
            float4 kv = *reinterpret_cast<const float4*>(&Kb[(size_t)(j0 + r) * 64 + c4]);
            Ks[r * PA + c4 + 0] = f2tf32(kv.x);
            Ks[r * PA + c4 + 1] = f2tf32(kv.y);
            Ks[r * PA + c4 + 2] = f2tf32(kv.z);
            Ks[r * PA + c4 + 3] = f2tf32(kv.w);
            float4 vv = *reinterpret_cast<const float4*>(&Vb[(size_t)(j0 + r) * 64 + c4]);
            Vs[r * PA + c4 + 0] = f2tf32(vv.x);
            Vs[r * PA + c4 + 1] = f2tf32(vv.y);
            Vs[r * PA + c4 + 2] = f2tf32(vv.z);
            Vs[r * PA + c4 + 3] = f2tf32(vv.w);
        }
        __syncthreads();

        // S = Q K^T  (warp: 16 x 64)
        float sacc[8][4];
#pragma unroll
        for (int n = 0; n < 8; n++)
#pragma unroll
            for (int f = 0; f < 4; f++) sacc[n][f] = 0.f;
#pragma unroll
        for (int k = 0; k < 8; k++) {
#pragma unroll
            for (int n = 0; n < 8; n++) {
                unsigned b0 = Ks[(n * 8 + g) * PA + k * 8 + t];
                unsigned b1 = Ks[(n * 8 + g) * PA + k * 8 + 4 + t];
                mma_tf32(sacc[n][0], sacc[n][1], sacc[n][2], sacc[n][3],
                         qf[k][0], qf[k][1], qf[k][2], qf[k][3], b0, b1);
            }
        }

        // online softmax (rows wr+g and wr+g+8), exp2 on FMA pipe
        float tm0 = -1e30f, tm1 = -1e30f;
#pragma unroll
        for (int n = 0; n < 8; n++) {
            tm0 = fmaxf(tm0, fmaxf(sacc[n][0], sacc[n][1]));
            tm1 = fmaxf(tm1, fmaxf(sacc[n][2], sacc[n][3]));
        }
        tm0 = fmaxf(tm0, __shfl_xor_sync(0xffffffffu, tm0, 1));
        tm0 = fmaxf(tm0, __shfl_xor_sync(0xffffffffu, tm0, 2));
        tm1 = fmaxf(tm1, __shfl_xor_sync(0xffffffffu, tm1, 1));
        tm1 = fmaxf(tm1, __shfl_xor_sync(0xffffffffu, tm1, 2));
        float mn0 = fmaxf(m0, tm0), mn1 = fmaxf(m1, tm1);
        float sc0 = fexp2(m0 - mn0), sc1 = fexp2(m1 - mn1);
        float ps0 = 0.f, ps1 = 0.f;
#pragma unroll
        for (int n = 0; n < 8; n++) {
            float p0 = fexp2(sacc[n][0] - mn0);
            float p1 = fexp2(sacc[n][1] - mn0);
            float p2 = fexp2(sacc[n][2] - mn1);
            float p3 = fexp2(sacc[n][3] - mn1);
            ps0 += p0 + p1; ps1 += p2 + p3;
            Ps[(wr + g)     * PA + n * 8 + 2 * t]     = f2tf32(p0);
            Ps[(wr + g)     * PA + n * 8 + 2 * t + 1] = f2tf32(p1);
            Ps[(wr + g + 8) * PA + n * 8 + 2 * t]     = f2tf32(p2);
            Ps[(wr + g + 8) * PA + n * 8 + 2 * t + 1] = f2tf32(p3);
            accO[n][0] *= sc0; accO[n][1] *= sc0;
            accO[n][2] *= sc1; accO[n][3] *= sc1;
        }
        ps0 += __shfl_xor_sync(0xffffffffu, ps0, 1);
        ps0 += __shfl_xor_sync(0xffffffffu, ps0, 2);
        ps1 += __shfl_xor_sync(0xffffffffu, ps1, 1);
        ps1 += __shfl_xor_sync(0xffffffffu, ps1, 2);
        l0 = l0 * sc0 + ps0;
        l1 = l1 * sc1 + ps1;
        m0 = mn0; m1 = mn1;
        __syncwarp();   // P staging is warp-private

        // O += P V   (A-frags from Ps, B-frags from Vs with (k,n) index swap)
#pragma unroll
        for (int k = 0; k < 8; k++) {
            unsigned a0 = Ps[(wr + g)     * PA + k * 8 + t];
            unsigned a1 = Ps[(wr + g + 8) * PA + k * 8 + t];
            unsigned a2 = Ps[(wr + g)     * PA + k * 8 + 4 + t];
            unsigned a3 = Ps[(wr + g + 8) * PA + k * 8 + 4 + t];
#pragma unroll
            for (int n = 0; n < 8; n++) {
                unsigned b0 = Vs[(k * 8 + t)     * PA + n * 8 + g];
                unsigned b1 = Vs[(k * 8 + t + 4) * PA + n * 8 + g];
                mma_tf32(accO[n][0], accO[n][1], accO[n][2], accO[n][3],
                         a0, a1, a2, a3, b0, b1);
            }
        }
        __syncthreads();  // before next tile overwrites Ks/Vs
    }

    // epilogue: normalize, write [b, s, h*64+vd]
    float inv0 = 1.f / l0, inv1 = 1.f / l1;
    int row0 = i0 + wr + g, row1 = row0 + 8;
#pragma unroll
    for (int n = 0; n < 8; n++) {
        int col = h * 64 + n * 8 + 2 * t;
        float2 o0, o1;
        o0.x = accO[n][0] * inv0; o0.y = accO[n][1] * inv0;
        o1.x = accO[n][2] * inv1; o1.y = accO[n][3] * inv1;
        *reinterpret_cast<float2*>(&g_ao[(size_t)(b * S_ + row0) * NV + col]) = o0;
        *reinterpret_cast<float2*>(&g_ao[(size_t)(b * S_ + row1) * NV + col]) = o1;
    }
}

// ---------------------------------------------------------------------------
// LN stats reduce + finalize
// ---------------------------------------------------------------------------
__global__ void stats_reduce()
{
    int w = threadIdx.x >> 5, lane = threadIdx.x & 31;
    float s = g_psum[w * 64 + lane] + g_psum[w * 64 + 32 + lane];
    float q = g_psq [w * 64 + lane] + g_psq [w * 64 + 32 + lane];
#pragma unroll
    for (int off = 16; off > 0; off >>= 1) {
        s += __shfl_down_sync(0xffffffffu, s, off);
        q += __shfl_down_sync(0xffffffffu, q, off);
    }
    if (lane == 0) { g_stats[2 * w] = s; g_stats[2 * w + 1] = q; }
}

__global__ void ln_finalize(float* __restrict__ y,
                            const float* __restrict__ lnw,
                            const float* __restrict__ lnb)
{
    int idx = blockIdx.x * 256 + threadIdx.x;
    int b   = idx >> 18;
    int sd4 = idx & ((1 << 18) - 1);
    const float invn = 1.0f / 1048576.0f;
    float mean = g_stats[2 * b] * invn;
    float var  = g_stats[2 * b + 1] * invn - mean * mean;
    float inv  = rsqrtf(var + 1e-5f);
    float4 v  = reinterpret_cast<float4*>(y)[idx];
    float4 w  = reinterpret_cast<const float4*>(lnw)[sd4];
    float4 bb = reinterpret_cast<const float4*>(lnb)[sd4];
    v.x = (v.x - mean) * inv * w.x + bb.x;
    v.y = (v.y - mean) * inv * w.y + bb.y;
    v.z = (v.z - mean) * inv * w.z + bb.z;
    v.w = (v.w - mean) * inv * w.w + bb.w;
    reinterpret_cast<float4*>(y)[idx] = v;
}

// ---------------------------------------------------------------------------
// kernel_launch
// ---------------------------------------------------------------------------
extern "C" void kernel_launch(void* const* d_in, const int* in_sizes, int n_in,
                              void* d_out, int out_size)
{
    const float* x    = (const float*)d_in[0];
    const float* W_qk = (const float*)d_in[1];
    const float* b_qk = (const float*)d_in[2];
    const float* W_v  = (const float*)d_in[3];
    const float* b_v  = (const float*)d_in[4];
    const float* W_o  = (const float*)d_in[5];
    const float* b_o  = (const float*)d_in[6];
    const float* ln_w = (const float*)d_in[7];
    const float* ln_b = (const float*)d_in[8];
    float* out = (float*)d_out;

    void *p_qk, *p_v, *p_ao;
    cudaGetSymbolAddress(&p_qk, g_qk);
    cudaGetSymbolAddress(&p_v,  g_v);
    cudaGetSymbolAddress(&p_ao, g_ao);

    cudaFuncSetAttribute(attn_tc_kernel, cudaFuncAttributeMaxDynamicSharedMemorySize,
                         AT_SMEM_BYTES);

    // 1) qk = x @ W_qk^T + b_qk   (8192 x 2048) — TF32 MMA
    tgemm_bias<<<dim3(NQK / 128, MROWS / 128), 256>>>(x, W_qk, b_qk, (float*)p_qk, NQK);
    // 2) v  = x @ W_v^T + b_v     (8192 x 1024) — TF32 MMA
    tgemm_bias<<<dim3(NV / 128, MROWS / 128), 256>>>(x, W_v, b_v, (float*)p_v, NV);
    // 3) repack into [b,h,s,64]
    repack_kernel<<<MROWS, 256>>>();
    // 4) flash attention — TF32 MMA + FMA-pipe exp2
    attn_tc_kernel<<<dim3(S_ / 128, H_, B_), 256, AT_SMEM_BYTES>>>();
    // 5) O-proj (TF32 MMA) + bias + residual + partial LN stats
    tgemm_oproj<<<dim3(NV / 128, MROWS / 128), 256>>>((const float*)p_ao, W_o, b_o, x, out);
    // 6) reduce stats per batch
    stats_reduce<<<1, 256>>>();
    // 7) LayerNorm finalize
    ln_finalize<<<(B_ * S_ * D_ / 4) / 256, 256>>>(out, ln_w, ln_b);
}